// round 12
// baseline (speedup 1.0000x reference)
#include <cuda_runtime.h>
#include <cstdint>
#include <math.h>

#define IN_DIM 256
#define HIDDEN 64
#define MAX_NODES 100000
#define NB 148          // exactly one wave: guaranteed co-resident on 148+ SMs
#define NT 512
#define NTH (NB * NT)   // 75776 threads
#define NWARP (NB * (NT / 32))

// Pipeline state (allocation-free: __device__ globals)
__device__ float g_z[MAX_NODES];      // x @ wv
__device__ float g_zs[MAX_NODES];     // dinv * z
__device__ float g_dinv[MAX_NODES];   // (deg+1)^-1/2
__device__ float g_aggs[MAX_NODES];   // edge-sum aggregate
__device__ int   g_degcnt[MAX_NODES];

// Software grid barrier state (generation counter; persists across replays)
__device__ unsigned g_count;
__device__ volatile unsigned g_gen;

__device__ __forceinline__ void gbar() {
    __syncthreads();
    if (threadIdx.x == 0) {
        __threadfence();
        unsigned gen = g_gen;
        if (atomicAdd(&g_count, 1u) == NB - 1) {
            g_count = 0;
            __threadfence();
            g_gen = gen + 1;
        } else {
            while (g_gen == gen) { __nanosleep(128); }
        }
        __threadfence();
    }
    __syncthreads();
}

// ---------------------------------------------------------------------------
// One persistent kernel, 5 phases, 4 grid barriers.
// ---------------------------------------------------------------------------
__global__ void __launch_bounds__(NT, 1)
fused_kernel(const float* __restrict__ x, const int* __restrict__ ei,
             const float* __restrict__ W, const float* __restrict__ b,
             const float* __restrict__ w2, const float* __restrict__ b2,
             float* __restrict__ out, int n, int E) {
    __shared__ float swv[IN_DIM];
    __shared__ float s_cst;
    __shared__ int   s_st;

    const int tid  = threadIdx.x;
    const int gtid = blockIdx.x * NT + tid;

    // ---- Phase A0: per-block redundant init (no cross-block dependency) ----
    if (tid < IN_DIM) {
        float s = 0.0f;
        #pragma unroll 8
        for (int j = 0; j < HIDDEN; j++) s = fmaf(W[tid * HIDDEN + j], w2[j], s);
        swv[tid] = s;
    }
    if (tid == 0) {
        float c = b2[0];
        for (int j = 0; j < HIDDEN; j++) c = fmaf(b[j], w2[j], c);
        s_cst = c;
        // dtype probe: int64 little-endian (<2^31) => odd 32-bit words all 0
        int nz = 0;
        #pragma unroll
        for (int i = 1; i < 128; i += 2) nz |= ei[i];
        s_st = (nz == 0) ? 2 : 1;
    }
    // zero counters (independent of z work)
    for (int i = gtid; i < n; i += NTH) { g_degcnt[i] = 0; g_aggs[i] = 0.0f; }
    __syncthreads();
    const int st = s_st;

    // ---- Phase A1: z = x @ wv  (warp per row, 2x float4 per lane) ----------
    {
        const int lane = tid & 31;
        const int gw   = blockIdx.x * (NT / 32) + (tid >> 5);
        const float4* wv4 = reinterpret_cast<const float4*>(swv);
        float4 w0 = wv4[lane], w1 = wv4[lane + 32];
        for (int row = gw; row < n; row += NWARP) {
            const float4* xr = reinterpret_cast<const float4*>(x + (size_t)row * IN_DIM);
            float4 a = xr[lane], c = xr[lane + 32];
            float p = a.x * w0.x + a.y * w0.y + a.z * w0.z + a.w * w0.w
                    + c.x * w1.x + c.y * w1.y + c.z * w1.z + c.w * w1.w;
            #pragma unroll
            for (int o = 16; o; o >>= 1) p += __shfl_xor_sync(0xffffffffu, p, o);
            if (lane == 0) g_z[row] = p;
        }
    }
    gbar();

    // ---- Phase B: in-degree histogram over dst row -------------------------
    if (st == 1) {
        const int4* d4p = reinterpret_cast<const int4*>(ei + E);
        int nc = E >> 2;
        for (int c = gtid; c < nc; c += NTH) {
            int4 d4 = d4p[c];
            atomicAdd(&g_degcnt[d4.x], 1);
            atomicAdd(&g_degcnt[d4.y], 1);
            atomicAdd(&g_degcnt[d4.z], 1);
            atomicAdd(&g_degcnt[d4.w], 1);
        }
        for (int e = (nc << 2) + gtid; e < E; e += NTH)
            atomicAdd(&g_degcnt[ei[E + e]], 1);
    } else {
        for (int e = gtid; e < E; e += NTH)
            atomicAdd(&g_degcnt[ei[(size_t)2 * (E + e)]], 1);
    }
    gbar();

    // ---- Phase C: dinv = rsqrt(deg+1); zs = dinv*z -------------------------
    for (int i = gtid; i < n; i += NTH) {
        float dv = rsqrtf((float)g_degcnt[i] + 1.0f);
        g_dinv[i] = dv;
        g_zs[i] = dv * g_z[i];
    }
    gbar();

    // ---- Phase D: scatter aggs[d] += zs[s] * dinv[d] (scalar fp32 RED) -----
    if (st == 1) {
        const int4* s4p = reinterpret_cast<const int4*>(ei);
        const int4* d4p = reinterpret_cast<const int4*>(ei + E);
        int nc = E >> 2;
        for (int c = gtid; c < nc; c += NTH) {
            int4 s4 = s4p[c];
            int4 d4 = d4p[c];
            atomicAdd(&g_aggs[d4.x], g_zs[s4.x] * g_dinv[d4.x]);
            atomicAdd(&g_aggs[d4.y], g_zs[s4.y] * g_dinv[d4.y]);
            atomicAdd(&g_aggs[d4.z], g_zs[s4.z] * g_dinv[d4.z]);
            atomicAdd(&g_aggs[d4.w], g_zs[s4.w] * g_dinv[d4.w]);
        }
        for (int e = (nc << 2) + gtid; e < E; e += NTH) {
            int s = ei[e], d = ei[E + e];
            atomicAdd(&g_aggs[d], g_zs[s] * g_dinv[d]);
        }
    } else {
        for (int e = gtid; e < E; e += NTH) {
            int s = ei[(size_t)2 * e];
            int d = ei[(size_t)2 * (E + e)];
            atomicAdd(&g_aggs[d], g_zs[s] * g_dinv[d]);
        }
    }
    gbar();

    // ---- Phase E: out = sigmoid(aggs + dinv*zs + cst) ----------------------
    const float cst = s_cst;
    for (int i = gtid; i < n; i += NTH) {
        float zv = g_aggs[i] + g_dinv[i] * g_zs[i] + cst;
        out[i] = 1.0f / (1.0f + __expf(-zv));
    }
}

// ---------------------------------------------------------------------------
extern "C" void kernel_launch(void* const* d_in, const int* in_sizes, int n_in,
                              void* d_out, int out_size) {
    const float* x  = (const float*)d_in[0];
    const int*   ei = (const int*)d_in[1];      // int32 words (or int64 pairs)
    const float* W  = (const float*)d_in[2];
    const float* b  = (const float*)d_in[3];
    const float* w2 = (const float*)d_in[4];
    const float* b2 = (const float*)d_in[5];
    float* out = (float*)d_out;

    int n = in_sizes[0] / IN_DIM;     // 100000
    int E = in_sizes[1] / 2;          // 1600000 elements per row

    fused_kernel<<<NB, NT>>>(x, ei, W, b, w2, b2, out, n, E);
}